// round 1
// baseline (speedup 1.0000x reference)
#include <cuda_runtime.h>

#define NN 100000
#define NE 1600000
#define FIN 20
#define HID 64
#define NG 2000

// ---------------- scratch (static device allocations; no cudaMalloc) ------
__device__ float g_deg[NN];
__device__ float g_dinv[NN];
__device__ float g_norm[NE];
__device__ float g_bufA[NN * HID];   // xw of current layer
__device__ float g_bufB[NN * HID];   // aggregated output / hidden state
__device__ float g_sums[NG * HID];
__device__ float g_cnts[NG];
__device__ int   g_i64;              // 1 if indices are int64, 0 if int32

// ---------------- helpers --------------------------------------------------
__device__ __forceinline__ int ld_idx(const void* p, long long i, int is64) {
    if (is64) return (int)((const long long*)p)[i];
    return ((const int*)p)[i];
}

__device__ __forceinline__ void red_add_v4(float* addr, float4 v) {
    asm volatile("red.global.add.v4.f32 [%0], {%1,%2,%3,%4};"
                 :: "l"(addr), "f"(v.x), "f"(v.y), "f"(v.z), "f"(v.w)
                 : "memory");
}

// ---------------- dtype detection -----------------------------------------
// If edge_index is int64 (values < 2^31), every odd 32-bit word is 0.
// If int32, odd words are random node ids in [0,100000) -> virtually surely nonzero.
__global__ void k_detect(const unsigned int* ei_words) {
    __shared__ int any_nz;
    if (threadIdx.x == 0) any_nz = 0;
    __syncthreads();
    unsigned int w = ei_words[2 * threadIdx.x + 1];
    if (w) atomicOr(&any_nz, 1);
    __syncthreads();
    if (threadIdx.x == 0) g_i64 = any_nz ? 0 : 1;
}

// ---------------- init: deg=1 (self loop), sums/cnts = 0 -------------------
__global__ void k_init() {
    int i = blockIdx.x * blockDim.x + threadIdx.x;
    if (i < NN) g_deg[i] = 1.0f;
    if (i < NG * HID) g_sums[i] = 0.0f;
    if (i < NG) g_cnts[i] = 0.0f;
}

// ---------------- degree ---------------------------------------------------
__global__ void k_deg(const void* ei) {
    int e = blockIdx.x * blockDim.x + threadIdx.x;
    if (e >= NE) return;
    int is64 = g_i64;
    int d = ld_idx(ei, (long long)NE + e, is64);
    atomicAdd(&g_deg[d], 1.0f);
}

__global__ void k_dinv() {
    int i = blockIdx.x * blockDim.x + threadIdx.x;
    if (i >= NN) return;
    g_dinv[i] = rsqrtf(g_deg[i]);  // deg >= 1 always (self-loop)
}

__global__ void k_norm(const void* ei) {
    int e = blockIdx.x * blockDim.x + threadIdx.x;
    if (e >= NE) return;
    int is64 = g_i64;
    int s = ld_idx(ei, e, is64);
    int d = ld_idx(ei, (long long)NE + e, is64);
    g_norm[e] = g_dinv[s] * g_dinv[d];
}

// ---------------- layer 1 GEMM: bufA = x @ W1  (K = 20) --------------------
__global__ void k_gemm1(const float* __restrict__ x, const float* __restrict__ W) {
    __shared__ float Ws[FIN * HID];   // 1280 floats
    __shared__ float Xs[16 * FIN];    // 320 floats
    int t = threadIdx.x;
    for (int i = t; i < FIN * HID; i += 256) Ws[i] = W[i];
    int n0 = blockIdx.x * 16;
    for (int i = t; i < 16 * FIN; i += 256) {
        int node = n0 + i / FIN;
        Xs[i] = (node < NN) ? x[(long long)node * FIN + (i % FIN)] : 0.0f;
    }
    __syncthreads();
    int node = n0 + (t >> 4);
    int c = t & 15;
    if (node >= NN) return;
    const float* xr = &Xs[(t >> 4) * FIN];
    float4 acc = make_float4(0.f, 0.f, 0.f, 0.f);
#pragma unroll
    for (int k = 0; k < FIN; k++) {
        float xk = xr[k];
        float4 w = *(const float4*)&Ws[k * HID + c * 4];
        acc.x += xk * w.x; acc.y += xk * w.y;
        acc.z += xk * w.z; acc.w += xk * w.w;
    }
    *(float4*)&g_bufA[node * HID + c * 4] = acc;
}

// ---------------- hidden GEMM: bufA = relu(bufB) @ W  (K = 64) -------------
__global__ void k_gemmh(const float* __restrict__ W) {
    __shared__ float Ws[HID * HID];   // 16 KB
    __shared__ float Xs[16 * HID];    // 4 KB
    int t = threadIdx.x;
    for (int i = t; i < HID * HID; i += 256) Ws[i] = W[i];
    int n0 = blockIdx.x * 16;
    for (int i = t; i < 16 * HID; i += 256) {
        int node = n0 + i / HID;
        Xs[i] = (node < NN) ? fmaxf(g_bufB[node * HID + (i % HID)], 0.0f) : 0.0f;
    }
    __syncthreads();
    int node = n0 + (t >> 4);
    int c = t & 15;
    if (node >= NN) return;
    const float* xr = &Xs[(t >> 4) * HID];
    float4 acc = make_float4(0.f, 0.f, 0.f, 0.f);
#pragma unroll
    for (int k = 0; k < HID; k++) {
        float xk = xr[k];
        float4 w = *(const float4*)&Ws[k * HID + c * 4];
        acc.x += xk * w.x; acc.y += xk * w.y;
        acc.z += xk * w.z; acc.w += xk * w.w;
    }
    *(float4*)&g_bufA[node * HID + c * 4] = acc;
}

// ---------------- self-loop + bias init: bufB = dinv^2 * bufA + b ----------
__global__ void k_selfinit(const float* __restrict__ b) {
    int gid = blockIdx.x * blockDim.x + threadIdx.x;
    if (gid >= NN * 16) return;
    int node = gid >> 4;
    int c = gid & 15;
    float di = g_dinv[node];
    float sl = di * di;
    float4 v = *(const float4*)&g_bufA[node * HID + c * 4];
    float4 b4 = *(const float4*)&b[c * 4];
    float4 o;
    o.x = sl * v.x + b4.x; o.y = sl * v.y + b4.y;
    o.z = sl * v.z + b4.z; o.w = sl * v.w + b4.w;
    *(float4*)&g_bufB[node * HID + c * 4] = o;
}

// ---------------- edge scatter: bufB[dst] += norm * bufA[src] --------------
__global__ void k_scatter(const void* ei) {
    int gid = blockIdx.x * blockDim.x + threadIdx.x;
    if (gid >= NE * 16) return;
    int e = gid >> 4;
    int c = gid & 15;
    int is64 = g_i64;
    int s = ld_idx(ei, e, is64);
    int d = ld_idx(ei, (long long)NE + e, is64);
    float nm = g_norm[e];
    float4 v = *(const float4*)&g_bufA[s * HID + c * 4];
    v.x *= nm; v.y *= nm; v.z *= nm; v.w *= nm;
    red_add_v4(&g_bufB[d * HID + c * 4], v);
}

// ---------------- pooling: sums[batch] += relu(bufB), cnts[batch] += 1 -----
__global__ void k_pool(const void* batch) {
    int gid = blockIdx.x * blockDim.x + threadIdx.x;
    if (gid >= NN * 16) return;
    int node = gid >> 4;
    int c = gid & 15;
    int is64 = g_i64;
    int g = ld_idx(batch, node, is64);
    float4 v = *(const float4*)&g_bufB[node * HID + c * 4];
    v.x = fmaxf(v.x, 0.f); v.y = fmaxf(v.y, 0.f);
    v.z = fmaxf(v.z, 0.f); v.w = fmaxf(v.w, 0.f);
    red_add_v4(&g_sums[g * HID + c * 4], v);
    if (c == 0) atomicAdd(&g_cnts[g], 1.0f);
}

// ---------------- final MLP head -------------------------------------------
__global__ void k_mlp(const float* __restrict__ lw1, const float* __restrict__ lb1,
                      const float* __restrict__ lw2, const float* __restrict__ lb2,
                      float* __restrict__ out) {
    int g = blockIdx.x;
    int j = threadIdx.x;  // 64 threads
    __shared__ float gs[HID];
    __shared__ float red[HID];
    float cnt = fmaxf(g_cnts[g], 1.0f);
    gs[j] = g_sums[g * HID + j] / cnt;
    __syncthreads();
    float t = lb1[j];
#pragma unroll
    for (int k = 0; k < HID; k++) t += gs[k] * lw1[k * HID + j];
    t = fmaxf(t, 0.0f);
    red[j] = t * lw2[j];
    __syncthreads();
    for (int s = 32; s > 0; s >>= 1) {
        if (j < s) red[j] += red[j + s];
        __syncthreads();
    }
    if (j == 0) out[g] = red[0] + lb2[0];
}

// ---------------- launch ----------------------------------------------------
extern "C" void kernel_launch(void* const* d_in, const int* in_sizes, int n_in,
                              void* d_out, int out_size) {
    const float* x   = (const float*)d_in[0];
    const float* W1  = (const float*)d_in[1];
    const float* b1  = (const float*)d_in[2];
    const float* W2  = (const float*)d_in[3];
    const float* b2  = (const float*)d_in[4];
    const float* W3  = (const float*)d_in[5];
    const float* b3  = (const float*)d_in[6];
    const float* lw1 = (const float*)d_in[7];
    const float* lb1 = (const float*)d_in[8];
    const float* lw2 = (const float*)d_in[9];
    const float* lb2 = (const float*)d_in[10];
    const void*  ei  = d_in[11];
    const void*  bat = d_in[12];

    const int T = 256;
    k_detect<<<1, 512>>>((const unsigned int*)ei);
    k_init<<<(NG * HID > NN ? NG * HID : NN + T - 1 + 0) / T + 1, T>>>();
    k_deg<<<(NE + T - 1) / T, T>>>(ei);
    k_dinv<<<(NN + T - 1) / T, T>>>();
    k_norm<<<(NE + T - 1) / T, T>>>(ei);

    int gNodes   = (NN + 15) / 16;
    int gElem    = (NN * 16 + T - 1) / T;
    int gScatter = (NE * 16 + T - 1) / T;

    // layer 1
    k_gemm1<<<gNodes, T>>>(x, W1);
    k_selfinit<<<gElem, T>>>(b1);
    k_scatter<<<gScatter, T>>>(ei);
    // layer 2
    k_gemmh<<<gNodes, T>>>(W2);
    k_selfinit<<<gElem, T>>>(b2);
    k_scatter<<<gScatter, T>>>(ei);
    // layer 3
    k_gemmh<<<gNodes, T>>>(W3);
    k_selfinit<<<gElem, T>>>(b3);
    k_scatter<<<gScatter, T>>>(ei);

    // pool + head
    k_pool<<<gElem, T>>>(bat);
    k_mlp<<<NG, HID>>>(lw1, lb1, lw2, lb2, (float*)d_out);
}

// round 2
// speedup vs baseline: 1.3411x; 1.3411x over previous
#include <cuda_runtime.h>

#define NN 100000
#define NE 1600000
#define FIN 20
#define HID 64
#define NG 2000
#define NB 391   // ceil(NN/256)

// ---------------- scratch (static device allocations) ----------------------
__device__ int   g_deg[NN];
__device__ float g_dinv[NN];
__device__ int   g_off[NN + 1];
__device__ int   g_bsum[512];
__device__ int   g_fill[NN];
__device__ int2  g_edges[NE];        // (src, bitcast(norm)) sorted by dst bucket
__device__ float g_bufA[NN * HID];   // xw of current layer
__device__ float g_bufB[NN * HID];   // aggregated output / hidden state
__device__ float g_sums[NG * HID];
__device__ float g_cnts[NG];
__device__ int   g_i64;              // 1 if indices are int64, 0 if int32

// ---------------- helpers ---------------------------------------------------
__device__ __forceinline__ int ld_idx(const void* p, long long i, int is64) {
    if (is64) return (int)((const long long*)p)[i];
    return ((const int*)p)[i];
}

__device__ __forceinline__ void red_add_v4(float* addr, float4 v) {
    asm volatile("red.global.add.v4.f32 [%0], {%1,%2,%3,%4};"
                 :: "l"(addr), "f"(v.x), "f"(v.y), "f"(v.z), "f"(v.w)
                 : "memory");
}

// ---------------- dtype detection ------------------------------------------
__global__ void k_detect(const unsigned int* ei_words) {
    __shared__ int any_nz;
    if (threadIdx.x == 0) any_nz = 0;
    __syncthreads();
    unsigned int w = ei_words[2 * threadIdx.x + 1];
    if (w) atomicOr(&any_nz, 1);
    __syncthreads();
    if (threadIdx.x == 0) g_i64 = any_nz ? 0 : 1;
}

// ---------------- init: zero counters ---------------------------------------
__global__ void k_init() {
    int i = blockIdx.x * blockDim.x + threadIdx.x;
    if (i < NN) { g_deg[i] = 0; g_fill[i] = 0; }
    if (i < NG * HID) g_sums[i] = 0.0f;
    if (i < NG) g_cnts[i] = 0.0f;
}

// ---------------- degree histogram (real edges only) -------------------------
__global__ void k_deg(const void* ei) {
    int e = blockIdx.x * blockDim.x + threadIdx.x;
    if (e >= NE) return;
    int is64 = g_i64;
    int d = ld_idx(ei, (long long)NE + e, is64);
    atomicAdd(&g_deg[d], 1);
}

__global__ void k_dinv() {
    int i = blockIdx.x * blockDim.x + threadIdx.x;
    if (i >= NN) return;
    g_dinv[i] = rsqrtf((float)g_deg[i] + 1.0f);   // +1 self-loop
}

// ---------------- CSR offsets: block sums -> scan -> per-block scan ----------
__global__ void k_bsum() {
    __shared__ int s[256];
    int i = blockIdx.x * 256 + threadIdx.x;
    s[threadIdx.x] = (i < NN) ? g_deg[i] : 0;
    __syncthreads();
    for (int st = 128; st > 0; st >>= 1) {
        if (threadIdx.x < st) s[threadIdx.x] += s[threadIdx.x + st];
        __syncthreads();
    }
    if (threadIdx.x == 0) g_bsum[blockIdx.x] = s[0];
}

__global__ void k_bscan() {     // 1 block, 512 threads, scans NB block sums
    __shared__ int s[512];
    int t = threadIdx.x;
    int own = (t < NB) ? g_bsum[t] : 0;
    s[t] = own;
    __syncthreads();
    for (int st = 1; st < 512; st <<= 1) {
        int v = (t >= st) ? s[t - st] : 0;
        __syncthreads();
        s[t] += v;
        __syncthreads();
    }
    if (t < NB) g_bsum[t] = s[t] - own;   // exclusive
}

__global__ void k_off() {
    __shared__ int s[256];
    int i = blockIdx.x * 256 + threadIdx.x;
    int own = (i < NN) ? g_deg[i] : 0;
    s[threadIdx.x] = own;
    __syncthreads();
    for (int st = 1; st < 256; st <<= 1) {
        int v = (threadIdx.x >= st) ? s[threadIdx.x - st] : 0;
        __syncthreads();
        s[threadIdx.x] += v;
        __syncthreads();
    }
    int excl = s[threadIdx.x] - own + g_bsum[blockIdx.x];
    if (i < NN) g_off[i] = excl;
    if (i == NN - 1) g_off[NN] = excl + own;
}

// ---------------- fill CSR edge records --------------------------------------
__global__ void k_fill(const void* ei) {
    int e = blockIdx.x * blockDim.x + threadIdx.x;
    if (e >= NE) return;
    int is64 = g_i64;
    int s = ld_idx(ei, e, is64);
    int d = ld_idx(ei, (long long)NE + e, is64);
    float nm = g_dinv[s] * g_dinv[d];
    int pos = g_off[d] + atomicAdd(&g_fill[d], 1);
    g_edges[pos] = make_int2(s, __float_as_int(nm));
}

// ---------------- layer 1 GEMM: bufA = x @ W1  (K = 20) ----------------------
__global__ void k_gemm1(const float* __restrict__ x, const float* __restrict__ W) {
    __shared__ float Ws[FIN * HID];
    __shared__ float Xs[16 * FIN];
    int t = threadIdx.x;
    for (int i = t; i < FIN * HID; i += 256) Ws[i] = W[i];
    int n0 = blockIdx.x * 16;
    for (int i = t; i < 16 * FIN; i += 256) {
        int node = n0 + i / FIN;
        Xs[i] = (node < NN) ? x[(long long)node * FIN + (i % FIN)] : 0.0f;
    }
    __syncthreads();
    int node = n0 + (t >> 4);
    int c = t & 15;
    if (node >= NN) return;
    const float* xr = &Xs[(t >> 4) * FIN];
    float4 acc = make_float4(0.f, 0.f, 0.f, 0.f);
#pragma unroll
    for (int k = 0; k < FIN; k++) {
        float xk = xr[k];
        float4 w = *(const float4*)&Ws[k * HID + c * 4];
        acc.x += xk * w.x; acc.y += xk * w.y;
        acc.z += xk * w.z; acc.w += xk * w.w;
    }
    *(float4*)&g_bufA[node * HID + c * 4] = acc;
}

// ---------------- hidden GEMM: bufA = relu(bufB) @ W  (K = 64) ---------------
__global__ void k_gemmh(const float* __restrict__ W) {
    __shared__ float Ws[HID * HID];
    __shared__ float Xs[16 * HID];
    int t = threadIdx.x;
    for (int i = t; i < HID * HID; i += 256) Ws[i] = W[i];
    int n0 = blockIdx.x * 16;
    for (int i = t; i < 16 * HID; i += 256) {
        int node = n0 + i / HID;
        Xs[i] = (node < NN) ? fmaxf(g_bufB[node * HID + (i % HID)], 0.0f) : 0.0f;
    }
    __syncthreads();
    int node = n0 + (t >> 4);
    int c = t & 15;
    if (node >= NN) return;
    const float* xr = &Xs[(t >> 4) * HID];
    float4 acc = make_float4(0.f, 0.f, 0.f, 0.f);
#pragma unroll
    for (int k = 0; k < HID; k++) {
        float xk = xr[k];
        float4 w = *(const float4*)&Ws[k * HID + c * 4];
        acc.x += xk * w.x; acc.y += xk * w.y;
        acc.z += xk * w.z; acc.w += xk * w.w;
    }
    *(float4*)&g_bufA[node * HID + c * 4] = acc;
}

// ---------------- gather aggregate: bufB[d] = sl*bufA[d] + b + sum norm*bufA[s]
__global__ void k_gather(const float* __restrict__ b) {
    int gid = blockIdx.x * blockDim.x + threadIdx.x;
    if (gid >= NN * 16) return;
    int node = gid >> 4;
    int c = gid & 15;

    float di = g_dinv[node];
    float sl = di * di;
    float4 v = *(const float4*)&g_bufA[node * HID + c * 4];
    float4 b4 = *(const float4*)&b[c * 4];
    float4 acc;
    acc.x = sl * v.x + b4.x; acc.y = sl * v.y + b4.y;
    acc.z = sl * v.z + b4.z; acc.w = sl * v.w + b4.w;

    int e0 = g_off[node];
    int e1 = g_off[node + 1];
    int e = e0;
    for (; e + 1 < e1; e += 2) {
        int2 p0 = g_edges[e];
        int2 p1 = g_edges[e + 1];
        float4 v0 = *(const float4*)&g_bufA[p0.x * HID + c * 4];
        float4 v1 = *(const float4*)&g_bufA[p1.x * HID + c * 4];
        float n0 = __int_as_float(p0.y);
        float n1 = __int_as_float(p1.y);
        acc.x += n0 * v0.x + n1 * v1.x;
        acc.y += n0 * v0.y + n1 * v1.y;
        acc.z += n0 * v0.z + n1 * v1.z;
        acc.w += n0 * v0.w + n1 * v1.w;
    }
    if (e < e1) {
        int2 p = g_edges[e];
        float4 v0 = *(const float4*)&g_bufA[p.x * HID + c * 4];
        float nm = __int_as_float(p.y);
        acc.x += nm * v0.x; acc.y += nm * v0.y;
        acc.z += nm * v0.z; acc.w += nm * v0.w;
    }
    *(float4*)&g_bufB[node * HID + c * 4] = acc;
}

// ---------------- pooling -----------------------------------------------------
__global__ void k_pool(const void* batch) {
    int gid = blockIdx.x * blockDim.x + threadIdx.x;
    if (gid >= NN * 16) return;
    int node = gid >> 4;
    int c = gid & 15;
    int is64 = g_i64;
    int g = ld_idx(batch, node, is64);
    float4 v = *(const float4*)&g_bufB[node * HID + c * 4];
    v.x = fmaxf(v.x, 0.f); v.y = fmaxf(v.y, 0.f);
    v.z = fmaxf(v.z, 0.f); v.w = fmaxf(v.w, 0.f);
    red_add_v4(&g_sums[g * HID + c * 4], v);
    if (c == 0) atomicAdd(&g_cnts[g], 1.0f);
}

// ---------------- final MLP head ----------------------------------------------
__global__ void k_mlp(const float* __restrict__ lw1, const float* __restrict__ lb1,
                      const float* __restrict__ lw2, const float* __restrict__ lb2,
                      float* __restrict__ out) {
    int g = blockIdx.x;
    int j = threadIdx.x;  // 64 threads
    __shared__ float gs[HID];
    __shared__ float red[HID];
    float cnt = fmaxf(g_cnts[g], 1.0f);
    gs[j] = g_sums[g * HID + j] / cnt;
    __syncthreads();
    float t = lb1[j];
#pragma unroll
    for (int k = 0; k < HID; k++) t += gs[k] * lw1[k * HID + j];
    t = fmaxf(t, 0.0f);
    red[j] = t * lw2[j];
    __syncthreads();
    for (int s = 32; s > 0; s >>= 1) {
        if (j < s) red[j] += red[j + s];
        __syncthreads();
    }
    if (j == 0) out[g] = red[0] + lb2[0];
}

// ---------------- launch --------------------------------------------------------
extern "C" void kernel_launch(void* const* d_in, const int* in_sizes, int n_in,
                              void* d_out, int out_size) {
    const float* x   = (const float*)d_in[0];
    const float* W1  = (const float*)d_in[1];
    const float* b1  = (const float*)d_in[2];
    const float* W2  = (const float*)d_in[3];
    const float* b2  = (const float*)d_in[4];
    const float* W3  = (const float*)d_in[5];
    const float* b3  = (const float*)d_in[6];
    const float* lw1 = (const float*)d_in[7];
    const float* lb1 = (const float*)d_in[8];
    const float* lw2 = (const float*)d_in[9];
    const float* lb2 = (const float*)d_in[10];
    const void*  ei  = d_in[11];
    const void*  bat = d_in[12];

    const int T = 256;
    k_detect<<<1, 512>>>((const unsigned int*)ei);
    k_init<<<(NG * HID + T - 1) / T, T>>>();
    k_deg<<<(NE + T - 1) / T, T>>>(ei);
    k_dinv<<<NB, T>>>();
    k_bsum<<<NB, T>>>();
    k_bscan<<<1, 512>>>();
    k_off<<<NB, T>>>();
    k_fill<<<(NE + T - 1) / T, T>>>(ei);

    int gNodes = (NN + 15) / 16;
    int gElem  = (NN * 16 + T - 1) / T;

    // layer 1
    k_gemm1<<<gNodes, T>>>(x, W1);
    k_gather<<<gElem, T>>>(b1);
    // layer 2
    k_gemmh<<<gNodes, T>>>(W2);
    k_gather<<<gElem, T>>>(b2);
    // layer 3
    k_gemmh<<<gNodes, T>>>(W3);
    k_gather<<<gElem, T>>>(b3);

    // pool + head
    k_pool<<<gElem, T>>>(bat);
    k_mlp<<<NG, HID>>>(lw1, lb1, lw2, lb2, (float*)d_out);
}

// round 3
// speedup vs baseline: 1.5979x; 1.1916x over previous
#include <cuda_runtime.h>
#include <cuda_fp16.h>

#define NN 100000
#define NE 1600000
#define FIN 20
#define HID 64
#define NG 2000
#define NB 391   // ceil(NN/256)

// ---------------- scratch ----------------------------------------------------
__device__ int    g_deg[NN];
__device__ float  g_dinv[NN];
__device__ int    g_off[NN + 1];
__device__ int    g_bsum[512];
__device__ int    g_fill[NN];
__device__ int2   g_edges[NE];         // (src, bitcast(norm)), bucketed by dst
__device__ __half g_x16[NN * 32];      // x in fp16, row stride 32 (20 valid)
__device__ float  g_agg1[NN * 24];     // aggregated x, row stride 24 (20 valid)
__device__ __half g_h16[NN * HID];     // relu(h) in fp16 (gather payload)
__device__ float  g_bufA[NN * HID];    // aggregated hidden (fp32)
__device__ float  g_sums[NG * HID];
__device__ float  g_cnts[NG];
__device__ int    g_i64;

// ---------------- helpers -----------------------------------------------------
__device__ __forceinline__ int ld_idx(const void* p, long long i, int is64) {
    if (is64) return (int)((const long long*)p)[i];
    return ((const int*)p)[i];
}

__device__ __forceinline__ void red_add_v4(float* addr, float4 v) {
    asm volatile("red.global.add.v4.f32 [%0], {%1,%2,%3,%4};"
                 :: "l"(addr), "f"(v.x), "f"(v.y), "f"(v.z), "f"(v.w)
                 : "memory");
}

// convert uint4 (8 halves) -> 8 floats, fma into acc with scale s
__device__ __forceinline__ void fma8_h(const uint4 u, float s, float* acc) {
    float2 f0 = __half22float2(*(const __half2*)&u.x);
    float2 f1 = __half22float2(*(const __half2*)&u.y);
    float2 f2 = __half22float2(*(const __half2*)&u.z);
    float2 f3 = __half22float2(*(const __half2*)&u.w);
    acc[0] += s * f0.x; acc[1] += s * f0.y;
    acc[2] += s * f1.x; acc[3] += s * f1.y;
    acc[4] += s * f2.x; acc[5] += s * f2.y;
    acc[6] += s * f3.x; acc[7] += s * f3.y;
}

// ---------------- dtype detection ----------------------------------------------
__global__ void k_detect(const unsigned int* ei_words) {
    __shared__ int any_nz;
    if (threadIdx.x == 0) any_nz = 0;
    __syncthreads();
    unsigned int w = ei_words[2 * threadIdx.x + 1];
    if (w) atomicOr(&any_nz, 1);
    __syncthreads();
    if (threadIdx.x == 0) g_i64 = any_nz ? 0 : 1;
}

// ---------------- init -----------------------------------------------------------
__global__ void k_init() {
    int i = blockIdx.x * blockDim.x + threadIdx.x;
    if (i < NN) g_deg[i] = 0;
    if (i < NG * HID) g_sums[i] = 0.0f;
    if (i < NG) g_cnts[i] = 0.0f;
}

// ---------------- degree histogram ------------------------------------------------
__global__ void k_deg(const void* ei) {
    int e = blockIdx.x * blockDim.x + threadIdx.x;
    if (e >= NE) return;
    int d = ld_idx(ei, (long long)NE + e, g_i64);
    atomicAdd(&g_deg[d], 1);
}

// ---------------- dinv + per-block sums -------------------------------------------
__global__ void k_dinvbsum() {
    __shared__ int s[256];
    int i = blockIdx.x * 256 + threadIdx.x;
    int d = (i < NN) ? g_deg[i] : 0;
    if (i < NN) g_dinv[i] = rsqrtf((float)d + 1.0f);
    s[threadIdx.x] = d;
    __syncthreads();
    for (int st = 128; st > 0; st >>= 1) {
        if (threadIdx.x < st) s[threadIdx.x] += s[threadIdx.x + st];
        __syncthreads();
    }
    if (threadIdx.x == 0) g_bsum[blockIdx.x] = s[0];
}

__global__ void k_bscan() {
    __shared__ int s[512];
    int t = threadIdx.x;
    int own = (t < NB) ? g_bsum[t] : 0;
    s[t] = own;
    __syncthreads();
    for (int st = 1; st < 512; st <<= 1) {
        int v = (t >= st) ? s[t - st] : 0;
        __syncthreads();
        s[t] += v;
        __syncthreads();
    }
    if (t < NB) g_bsum[t] = s[t] - own;
}

__global__ void k_off() {
    __shared__ int s[256];
    int i = blockIdx.x * 256 + threadIdx.x;
    int own = (i < NN) ? g_deg[i] : 0;
    s[threadIdx.x] = own;
    __syncthreads();
    for (int st = 1; st < 256; st <<= 1) {
        int v = (threadIdx.x >= st) ? s[threadIdx.x - st] : 0;
        __syncthreads();
        s[threadIdx.x] += v;
        __syncthreads();
    }
    int excl = s[threadIdx.x] - own + g_bsum[blockIdx.x];
    if (i < NN) { g_off[i] = excl; g_fill[i] = excl; }
    if (i == NN - 1) g_off[NN] = excl + own;
}

// ---------------- fill CSR ------------------------------------------------------
__global__ void k_fill(const void* ei) {
    int e = blockIdx.x * blockDim.x + threadIdx.x;
    if (e >= NE) return;
    int is64 = g_i64;
    int s = ld_idx(ei, e, is64);
    int d = ld_idx(ei, (long long)NE + e, is64);
    float nm = g_dinv[s] * g_dinv[d];
    int pos = atomicAdd(&g_fill[d], 1);
    g_edges[pos] = make_int2(s, __float_as_int(nm));
}

// ---------------- x -> fp16 padded ------------------------------------------------
__global__ void k_x2h(const float* __restrict__ x) {
    int gid = blockIdx.x * blockDim.x + threadIdx.x;
    if (gid >= NN * 32) return;
    int node = gid >> 5;
    int f = gid & 31;
    float v = (f < FIN) ? x[(long long)node * FIN + f] : 0.0f;
    g_x16[gid] = __float2half_rn(v);
}

// ---------------- gather over x (20 dims): agg1 = A_norm @ x ------------------------
__global__ void k_gather1() {
    int gid = blockIdx.x * blockDim.x + threadIdx.x;
    if (gid >= NN * 4) return;
    int node = gid >> 2;
    int c = gid & 3;              // 8 halves per thread

    float acc[8] = {0, 0, 0, 0, 0, 0, 0, 0};
    float di = g_dinv[node];
    float sl = di * di;
    uint4 own = *(const uint4*)&g_x16[node * 32 + c * 8];
    fma8_h(own, sl, acc);

    int e0 = g_off[node], e1 = g_off[node + 1];
    int e = e0;
    for (; e + 1 < e1; e += 2) {
        int2 p0 = g_edges[e];
        int2 p1 = g_edges[e + 1];
        uint4 u0 = *(const uint4*)&g_x16[p0.x * 32 + c * 8];
        uint4 u1 = *(const uint4*)&g_x16[p1.x * 32 + c * 8];
        fma8_h(u0, __int_as_float(p0.y), acc);
        fma8_h(u1, __int_as_float(p1.y), acc);
    }
    if (e < e1) {
        int2 p = g_edges[e];
        uint4 u = *(const uint4*)&g_x16[p.x * 32 + c * 8];
        fma8_h(u, __int_as_float(p.y), acc);
    }
    // store: row stride 24 floats; valid floats 0..19
    float* dst = &g_agg1[node * 24];
    if (c < 2) {
        *(float4*)&dst[c * 8]     = make_float4(acc[0], acc[1], acc[2], acc[3]);
        *(float4*)&dst[c * 8 + 4] = make_float4(acc[4], acc[5], acc[6], acc[7]);
    } else if (c == 2) {
        *(float4*)&dst[16] = make_float4(acc[0], acc[1], acc[2], acc[3]);
    }
}

// ---------------- GEMM1: h16 = relu(agg1 @ W1 + b1)  (K=20) -------------------------
__global__ void k_gemm1(const float* __restrict__ W, const float* __restrict__ b) {
    __shared__ float Ws[FIN * HID];
    __shared__ float Xs[16 * 24];
    int t = threadIdx.x;
    for (int i = t; i < FIN * HID; i += 256) Ws[i] = W[i];
    int n0 = blockIdx.x * 16;
    for (int i = t; i < 16 * 24; i += 256) {
        int node = n0 + i / 24;
        Xs[i] = (node < NN) ? g_agg1[node * 24 + (i % 24)] : 0.0f;
    }
    __syncthreads();
    int node = n0 + (t >> 4);
    int c = t & 15;
    if (node >= NN) return;
    const float* xr = &Xs[(t >> 4) * 24];
    float4 acc = *(const float4*)&b[c * 4];
#pragma unroll
    for (int k = 0; k < FIN; k++) {
        float xk = xr[k];
        float4 w = *(const float4*)&Ws[k * HID + c * 4];
        acc.x += xk * w.x; acc.y += xk * w.y;
        acc.z += xk * w.z; acc.w += xk * w.w;
    }
    __half2 h0 = __floats2half2_rn(fmaxf(acc.x, 0.f), fmaxf(acc.y, 0.f));
    __half2 h1 = __floats2half2_rn(fmaxf(acc.z, 0.f), fmaxf(acc.w, 0.f));
    uint2 pk = make_uint2(*(unsigned*)&h0, *(unsigned*)&h1);
    *(uint2*)&g_h16[node * HID + c * 4] = pk;
}

// ---------------- gather hidden (64 dims): bufA = A_norm @ h16 ----------------------
__global__ void k_gatherh() {
    int gid = blockIdx.x * blockDim.x + threadIdx.x;
    if (gid >= NN * 8) return;
    int node = gid >> 3;
    int c = gid & 7;              // 8 halves per thread

    float acc[8] = {0, 0, 0, 0, 0, 0, 0, 0};
    float di = g_dinv[node];
    float sl = di * di;
    uint4 own = *(const uint4*)&g_h16[node * HID + c * 8];
    fma8_h(own, sl, acc);

    int e0 = g_off[node], e1 = g_off[node + 1];
    int e = e0;
    for (; e + 1 < e1; e += 2) {
        int2 p0 = g_edges[e];
        int2 p1 = g_edges[e + 1];
        uint4 u0 = *(const uint4*)&g_h16[p0.x * HID + c * 8];
        uint4 u1 = *(const uint4*)&g_h16[p1.x * HID + c * 8];
        fma8_h(u0, __int_as_float(p0.y), acc);
        fma8_h(u1, __int_as_float(p1.y), acc);
    }
    if (e < e1) {
        int2 p = g_edges[e];
        uint4 u = *(const uint4*)&g_h16[p.x * HID + c * 8];
        fma8_h(u, __int_as_float(p.y), acc);
    }
    float* dst = &g_bufA[node * HID + c * 8];
    *(float4*)&dst[0] = make_float4(acc[0], acc[1], acc[2], acc[3]);
    *(float4*)&dst[4] = make_float4(acc[4], acc[5], acc[6], acc[7]);
}

// ---------------- GEMM hidden: h16 = relu(bufA @ W + b)  (K=64) ---------------------
__global__ void k_gemmh(const float* __restrict__ W, const float* __restrict__ b) {
    __shared__ float Ws[HID * HID];
    __shared__ float Xs[16 * HID];
    int t = threadIdx.x;
    for (int i = t; i < HID * HID; i += 256) Ws[i] = W[i];
    int n0 = blockIdx.x * 16;
    for (int i = t; i < 16 * HID; i += 256) {
        int node = n0 + i / HID;
        Xs[i] = (node < NN) ? g_bufA[node * HID + (i % HID)] : 0.0f;
    }
    __syncthreads();
    int node = n0 + (t >> 4);
    int c = t & 15;
    if (node >= NN) return;
    const float* xr = &Xs[(t >> 4) * HID];
    float4 acc = *(const float4*)&b[c * 4];
#pragma unroll
    for (int k = 0; k < HID; k++) {
        float xk = xr[k];
        float4 w = *(const float4*)&Ws[k * HID + c * 4];
        acc.x += xk * w.x; acc.y += xk * w.y;
        acc.z += xk * w.z; acc.w += xk * w.w;
    }
    __half2 h0 = __floats2half2_rn(fmaxf(acc.x, 0.f), fmaxf(acc.y, 0.f));
    __half2 h1 = __floats2half2_rn(fmaxf(acc.z, 0.f), fmaxf(acc.w, 0.f));
    uint2 pk = make_uint2(*(unsigned*)&h0, *(unsigned*)&h1);
    *(uint2*)&g_h16[node * HID + c * 4] = pk;
}

// ---------------- segmented pool over sorted batch ----------------------------------
#define NSTRIP 16
__global__ void k_pool(const void* batch) {
    int t = threadIdx.x;
    int grp = blockIdx.x * 32 + (t >> 3);
    int c = t & 7;
    int n0 = grp * NSTRIP;
    if (n0 >= NN) return;
    int n1 = n0 + NSTRIP; if (n1 > NN) n1 = NN;
    int is64 = g_i64;

    float acc[8] = {0, 0, 0, 0, 0, 0, 0, 0};
    float cnt = 0.0f;
    int cur = ld_idx(batch, n0, is64);
    for (int node = n0; node < n1; node++) {
        int g = ld_idx(batch, node, is64);
        if (g != cur) {
            red_add_v4(&g_sums[cur * HID + c * 8],
                       make_float4(acc[0], acc[1], acc[2], acc[3]));
            red_add_v4(&g_sums[cur * HID + c * 8 + 4],
                       make_float4(acc[4], acc[5], acc[6], acc[7]));
            if (c == 0) atomicAdd(&g_cnts[cur], cnt);
#pragma unroll
            for (int i = 0; i < 8; i++) acc[i] = 0.0f;
            cnt = 0.0f;
            cur = g;
        }
        uint4 u = *(const uint4*)&g_h16[node * HID + c * 8];
        fma8_h(u, 1.0f, acc);
        cnt += 1.0f;
    }
    red_add_v4(&g_sums[cur * HID + c * 8],
               make_float4(acc[0], acc[1], acc[2], acc[3]));
    red_add_v4(&g_sums[cur * HID + c * 8 + 4],
               make_float4(acc[4], acc[5], acc[6], acc[7]));
    if (c == 0) atomicAdd(&g_cnts[cur], cnt);
}

// ---------------- final MLP head ------------------------------------------------------
__global__ void k_mlp(const float* __restrict__ lw1, const float* __restrict__ lb1,
                      const float* __restrict__ lw2, const float* __restrict__ lb2,
                      float* __restrict__ out) {
    int g = blockIdx.x;
    int j = threadIdx.x;  // 64
    __shared__ float gs[HID];
    __shared__ float red[HID];
    float cnt = fmaxf(g_cnts[g], 1.0f);
    gs[j] = g_sums[g * HID + j] / cnt;
    __syncthreads();
    float t = lb1[j];
#pragma unroll
    for (int k = 0; k < HID; k++) t += gs[k] * lw1[k * HID + j];
    t = fmaxf(t, 0.0f);
    red[j] = t * lw2[j];
    __syncthreads();
    for (int s = 32; s > 0; s >>= 1) {
        if (j < s) red[j] += red[j + s];
        __syncthreads();
    }
    if (j == 0) out[g] = red[0] + lb2[0];
}

// ---------------- launch -----------------------------------------------------------------
extern "C" void kernel_launch(void* const* d_in, const int* in_sizes, int n_in,
                              void* d_out, int out_size) {
    const float* x   = (const float*)d_in[0];
    const float* W1  = (const float*)d_in[1];
    const float* b1  = (const float*)d_in[2];
    const float* W2  = (const float*)d_in[3];
    const float* b2  = (const float*)d_in[4];
    const float* W3  = (const float*)d_in[5];
    const float* b3  = (const float*)d_in[6];
    const float* lw1 = (const float*)d_in[7];
    const float* lb1 = (const float*)d_in[8];
    const float* lw2 = (const float*)d_in[9];
    const float* lb2 = (const float*)d_in[10];
    const void*  ei  = d_in[11];
    const void*  bat = d_in[12];

    const int T = 256;
    k_detect<<<1, 512>>>((const unsigned int*)ei);
    k_init<<<(NG * HID + T - 1) / T, T>>>();
    k_deg<<<(NE + T - 1) / T, T>>>(ei);
    k_dinvbsum<<<NB, T>>>();
    k_bscan<<<1, 512>>>();
    k_off<<<NB, T>>>();
    k_fill<<<(NE + T - 1) / T, T>>>(ei);
    k_x2h<<<(NN * 32 + T - 1) / T, T>>>(x);

    int gNodes = (NN + 15) / 16;

    // layer 1 (reassociated: aggregate x, then GEMM)
    k_gather1<<<(NN * 4 + T - 1) / T, T>>>();
    k_gemm1<<<gNodes, T>>>(W1, b1);
    // layer 2
    k_gatherh<<<(NN * 8 + T - 1) / T, T>>>();
    k_gemmh<<<gNodes, T>>>(W2, b2);
    // layer 3
    k_gatherh<<<(NN * 8 + T - 1) / T, T>>>();
    k_gemmh<<<gNodes, T>>>(W3, b3);

    // pool + head
    k_pool<<<(NN + 511) / 512, T>>>(bat);
    k_mlp<<<NG, HID>>>(lw1, lb1, lw2, lb2, (float*)d_out);
}